// round 16
// baseline (speedup 1.0000x reference)
#include <cuda_runtime.h>
#include <cuda_fp16.h>
#include <math.h>

// Problem dims (fixed by the dataset)
#define NN 4
#define HH 512
#define WW 512
#define CC 64

#define CPB     64                 // channels per tile = full row/column
#define THREADS 512
#define ROWLEN  512
#define NCHUNK  16
#define CLEN    (ROWLEN / NCHUNK)  // 32 (pass1)
#define LWARM   16                 // warm-up: err ~ 0.5^17 ~ 8e-6
#define H2PW    (CPB / 2)          // half2 per scan-site = 32
#define VECH    (ROWLEN * CPB / 8) // uint4 per full fp16 tile = 4096
#define SMEM_BYTES (ROWLEN * CPB * 2)   // 65536 (pass1 tile)

// pass2 half-column tiles
#define HROWS   256                // rows per pass2 block
#define CLEN2   (HROWS / NCHUNK)   // 16
#define VECH2   (HROWS * CPB / 8)  // 2048
#define SMEM2_BYTES (HROWS * CPB * 2)   // 32768 -> 4 CTAs/SM

#define ZCOL    (HH * CC)          // elements per z column blob = 32768

// W-filtered image, fp16, W-MAJOR layout: z[n][w][h][c].
__device__ __half g_scratch[(size_t)NN * HH * WW * CC];

// ---- pass1: R15 verbatim (smem copy-in, scan, w-major z stores) ----
__device__ __forceinline__ void iir_scan_tile_h2(__half2* s, int tid) {
    const int c     = tid & 31;
    const int chunk = tid >> 5;
    const int w0    = chunk * CLEN;
    const int w1    = w0 + CLEN;

    int ws = w0 - LWARM; if (ws < 0) ws = 0;
    float2 carry = __half22float2(s[ws * H2PW + c]);
    for (int w = ws; w < w0; ++w) {
        const float2 v = __half22float2(s[w * H2PW + c]);
        carry.x = fmaf(0.5f, carry.x, 0.5f * v.x);
        carry.y = fmaf(0.5f, carry.y, 0.5f * v.y);
    }
    __syncthreads();

    #pragma unroll
    for (int w = w0; w < w1; ++w) {
        const float2 v = __half22float2(s[w * H2PW + c]);
        carry.x = fmaf(0.5f, carry.x, 0.5f * v.x);
        carry.y = fmaf(0.5f, carry.y, 0.5f * v.y);
        s[w * H2PW + c] = __floats2half2_rn(carry.x, carry.y);
    }
    __syncthreads();

    int we = w1 - 1 + LWARM; if (we > ROWLEN - 1) we = ROWLEN - 1;
    carry = __half22float2(s[we * H2PW + c]);
    for (int w = we - 1; w >= w1; --w) {
        const float2 v = __half22float2(s[w * H2PW + c]);
        carry.x = fmaf(0.5f, carry.x, 0.5f * v.x);
        carry.y = fmaf(0.5f, carry.y, 0.5f * v.y);
    }
    __syncthreads();

    #pragma unroll
    for (int w = w1 - 1; w >= w0; --w) {
        const float2 v = __half22float2(s[w * H2PW + c]);
        carry.x = fmaf(0.5f, carry.x, 0.5f * v.x);
        carry.y = fmaf(0.5f, carry.y, 0.5f * v.y);
        s[w * H2PW + c] = __floats2half2_rn(carry.x, carry.y);
    }
    __syncthreads();
}

__global__ void __launch_bounds__(THREADS, 3)
pass1_kernel(const float* __restrict__ x) {
    extern __shared__ __half2 s2[];
    uint4* s4 = reinterpret_cast<uint4*>(s2);

    const int    nh    = blockIdx.x;                // n*HH + h
    const int    n     = nh >> 9;
    const int    h     = nh & 511;
    const size_t xbase = (size_t)nh * (WW * CC);
    const size_t zbase = ((size_t)n * WW) * ZCOL + (size_t)h * CC;

    #pragma unroll
    for (int i = threadIdx.x; i < VECH; i += THREADS) {
        const int w = i >> 3;
        const int q = i & 7;
        const float4 a = *(const float4*)(x + xbase + (size_t)w * CC + q * 8);
        const float4 b = *(const float4*)(x + xbase + (size_t)w * CC + q * 8 + 4);
        __half2 hv[4];
        hv[0] = __floats2half2_rn(a.x, a.y);
        hv[1] = __floats2half2_rn(a.z, a.w);
        hv[2] = __floats2half2_rn(b.x, b.y);
        hv[3] = __floats2half2_rn(b.z, b.w);
        s4[w * 8 + q] = *(uint4*)hv;
    }
    __syncthreads();

    iir_scan_tile_h2(s2, threadIdx.x);

    #pragma unroll
    for (int i = threadIdx.x; i < VECH; i += THREADS) {
        const int w = i >> 3;
        const int q = i & 7;
        *(uint4*)(g_scratch + zbase + (size_t)w * ZCOL + q * 8) = s4[w * 8 + q];
    }
}

// ---- pass2: half-column tiles (256 rows), 4 CTAs/SM ----
// Forward warm-up/scan read the contiguous z blob straight from gmem;
// backward warm-up: in-tile chunks use smem y_f; the tile-boundary chunk
// computes yb[g1] = sum_j 0.5^{j+1} y_f[g1+j] in one ascending gmem pass
// (forward-recur y_f while accumulating); last block uses the exact
// yb[511] = y_f[511] init. Epilogue reconstructs x from z[w-1,w,w+1].
__global__ void __launch_bounds__(THREADS, 4)
pass2_kernel(const float* __restrict__ alpha,
             float*       __restrict__ out) {
    extern __shared__ __half2 s2[];
    __shared__ __align__(16) float sm[CPB];

    const int    nw    = blockIdx.x;                // n*WW + w
    const int    G     = blockIdx.y * HROWS;        // global row base
    const int    n     = nw >> 9;
    const int    w     = nw & 511;
    const size_t zbase = ((size_t)n * WW + w) * ZCOL;
    const size_t obase = (size_t)n * (HH * WW * CC) + (size_t)w * CC;
    const __half* z0   = g_scratch + zbase;

    if (threadIdx.x < CPB)
        sm[threadIdx.x] = 1.0f / (1.0f + expf(-alpha[threadIdx.x]));

    const int c2 = threadIdx.x & 31;
    const int l0 = (threadIdx.x >> 5) * CLEN2;      // local rows
    const int l1 = l0 + CLEN2;
    const int g0 = G + l0;                          // global rows
    const int g1 = G + l1;

    // ---- forward warm-up: gmem fp16 z reads (global indices) ----
    int gs = g0 - LWARM; if (gs < 0) gs = 0;
    float2 carry = __half22float2(*(const __half2*)(z0 + (size_t)gs * CC + c2 * 2));
    for (int gh = gs; gh < g0; ++gh) {
        const float2 v = __half22float2(*(const __half2*)(z0 + (size_t)gh * CC + c2 * 2));
        carry.x = fmaf(0.5f, carry.x, 0.5f * v.x);
        carry.y = fmaf(0.5f, carry.y, 0.5f * v.y);
    }

    // ---- forward scan: gmem in, smem y_f out (local rows) ----
    #pragma unroll 8
    for (int h = l0; h < l1; ++h) {
        const float2 v = __half22float2(*(const __half2*)(z0 + (size_t)(G + h) * CC + c2 * 2));
        carry.x = fmaf(0.5f, carry.x, 0.5f * v.x);
        carry.y = fmaf(0.5f, carry.y, 0.5f * v.y);
        s2[h * H2PW + c2] = __floats2half2_rn(carry.x, carry.y);
    }
    __syncthreads();

    // ---- backward warm-up ----
    float2 cb;
    if (l1 + LWARM <= HROWS) {
        // in-tile: smem y_f rows [l1, l1+LWARM)
        const int le = l1 - 1 + LWARM;              // <= HROWS-1
        cb = __half22float2(s2[le * H2PW + c2]);
        for (int h = le - 1; h >= l1; --h) {
            const float2 v = __half22float2(s2[h * H2PW + c2]);
            cb.x = fmaf(0.5f, cb.x, 0.5f * v.x);
            cb.y = fmaf(0.5f, cb.y, 0.5f * v.y);
        }
    } else if (g1 >= ROWLEN) {
        // last chunk of last block: exact yb[511] = y_f[511]
        cb = __half22float2(s2[(HROWS - 1) * H2PW + c2]);
    } else {
        // tile-boundary chunk: ascending gmem pass over z.
        // 1) recompute y_f carry up to g1; 2) accumulate yb[g1].
        const int ys = g1 - LWARM;
        float2 yc = __half22float2(*(const __half2*)(z0 + (size_t)ys * CC + c2 * 2));
        for (int gh = ys; gh < g1; ++gh) {
            const float2 v = __half22float2(*(const __half2*)(z0 + (size_t)gh * CC + c2 * 2));
            yc.x = fmaf(0.5f, yc.x, 0.5f * v.x);
            yc.y = fmaf(0.5f, yc.y, 0.5f * v.y);
        }
        float2 acc = make_float2(0.f, 0.f);
        float  wgt = 0.5f;
        for (int gh = g1; gh < g1 + LWARM; ++gh) {
            const float2 v = __half22float2(*(const __half2*)(z0 + (size_t)gh * CC + c2 * 2));
            yc.x = fmaf(0.5f, yc.x, 0.5f * v.x);
            yc.y = fmaf(0.5f, yc.y, 0.5f * v.y);
            acc.x = fmaf(wgt, yc.x, acc.x);
            acc.y = fmaf(wgt, yc.y, acc.y);
            wgt *= 0.5f;
        }
        cb = acc;
    }
    __syncthreads();   // warm-up reads of neighbor smem before in-place writes

    // ---- backward scan, in place ----
    #pragma unroll
    for (int h = l1 - 1; h >= l0; --h) {
        const float2 v = __half22float2(s2[h * H2PW + c2]);
        cb.x = fmaf(0.5f, cb.x, 0.5f * v.x);
        cb.y = fmaf(0.5f, cb.y, 0.5f * v.y);
        s2[h * H2PW + c2] = __floats2half2_rn(cb.x, cb.y);
    }
    __syncthreads();

    // Exact inverse of the W filter:
    //   w in [1,510]: x = 5 z[w] - 2 z[w-1] - 2 z[w+1]
    //   w = 0:        x = 2 z[0] - z[1]
    //   w = 511:      x = 3 z[511] - 2 z[510]
    float cm, c0, cp;
    const __half *zm, *zp;
    if (w == 0)        { cm = 0.f;  c0 = 2.f; cp = -1.f;
                         zm = z0;          zp = z0 + ZCOL; }
    else if (w == 511) { cm = -2.f; c0 = 3.f; cp = 0.f;
                         zm = z0 - ZCOL;   zp = z0; }
    else               { cm = -2.f; c0 = 5.f; cp = -2.f;
                         zm = z0 - ZCOL;   zp = z0 + ZCOL; }

    // Epilogue over local rows (global gh = G + h); full MLP.
    #pragma unroll
    for (int i = threadIdx.x; i < VECH2; i += THREADS) {
        const int    h  = i >> 3;
        const int    q  = i & 7;
        const size_t zo = (size_t)(G + h) * CC + q * 8;
        const uint4  u0 = *(const uint4*)(z0 + zo);
        const uint4  um = *(const uint4*)(zm + zo);
        const uint4  up = *(const uint4*)(zp + zo);
        const __half2* hz0 = (const __half2*)&u0;
        const __half2* hzm = (const __half2*)&um;
        const __half2* hzp = (const __half2*)&up;
        const __half2* hy  = s2 + h * H2PW + q * 4;

        float outv[8];
        #pragma unroll
        for (int k = 0; k < 4; ++k) {
            const float2 v0 = __half22float2(hz0[k]);
            const float2 vm = __half22float2(hzm[k]);
            const float2 vp = __half22float2(hzp[k]);
            const float2 yv = __half22float2(hy[k]);
            const float2 mv = *(const float2*)(&sm[q * 8 + k * 2]);
            float xr, xi;
            xr = fmaf(c0, v0.x, fmaf(cm, vm.x, cp * vp.x));
            xi = fmaf(c0, v0.y, fmaf(cm, vm.y, cp * vp.y));
            outv[2 * k]     = fmaf(mv.x, yv.x - xr, xr);
            outv[2 * k + 1] = fmaf(mv.y, yv.y - xi, xi);
        }
        float* op = out + obase + (size_t)(G + h) * (WW * CC) + q * 8;
        *(float4*)op       = *(float4*)&outv[0];
        *(float4*)(op + 4) = *(float4*)&outv[4];
    }
}

extern "C" void kernel_launch(void* const* d_in, const int* in_sizes, int n_in,
                              void* d_out, int out_size) {
    const float* x     = (const float*)d_in[0];
    const float* alpha = (const float*)d_in[1];
    float*       out   = (float*)d_out;

    // >48KB dynamic smem opt-in for pass1 (idempotent, capture-safe).
    cudaFuncSetAttribute(pass1_kernel,
                         cudaFuncAttributeMaxDynamicSharedMemorySize, SMEM_BYTES);

    pass1_kernel<<<NN * HH, THREADS, SMEM_BYTES>>>(x);

    dim3 grid2(NN * WW, HH / HROWS);   // (2048, 2)
    pass2_kernel<<<grid2, THREADS, SMEM2_BYTES>>>(alpha, out);
}

// round 17
// speedup vs baseline: 1.2074x; 1.2074x over previous
#include <cuda_runtime.h>
#include <cuda_fp16.h>
#include <math.h>

// Problem dims (fixed by the dataset)
#define NN 4
#define HH 512
#define WW 512
#define CC 64

#define CPB     64                 // channels per tile = full row/column
#define THREADS 512
#define ROWLEN  512
#define NCHUNK  16
#define CLEN    (ROWLEN / NCHUNK)  // 32
#define LWARM   16                 // warm-up: err ~ 0.5^17 ~ 8e-6
#define H2PW    (CPB / 2)          // half2 per scan-site = 32
#define VECH    (ROWLEN * CPB / 8) // uint4 per full fp16 tile = 4096
#define SMEM_BYTES (ROWLEN * CPB * 2)   // 65536 (3 CTAs/SM)

#define ZCOL    (HH * CC)          // elements per z column blob = 32768
#define BATCH   8                  // backward-scan/epilogue fusion batch

// W-filtered image, fp16, W-MAJOR layout: z[n][w][h][c].
__device__ __half g_scratch[(size_t)NN * HH * WW * CC];

// ---- pass1: R15 verbatim (smem copy-in, scan, w-major z stores) ----
__device__ __forceinline__ void iir_scan_tile_h2(__half2* s, int tid) {
    const int c     = tid & 31;
    const int chunk = tid >> 5;
    const int w0    = chunk * CLEN;
    const int w1    = w0 + CLEN;

    int ws = w0 - LWARM; if (ws < 0) ws = 0;
    float2 carry = __half22float2(s[ws * H2PW + c]);
    for (int w = ws; w < w0; ++w) {
        const float2 v = __half22float2(s[w * H2PW + c]);
        carry.x = fmaf(0.5f, carry.x, 0.5f * v.x);
        carry.y = fmaf(0.5f, carry.y, 0.5f * v.y);
    }
    __syncthreads();

    #pragma unroll
    for (int w = w0; w < w1; ++w) {
        const float2 v = __half22float2(s[w * H2PW + c]);
        carry.x = fmaf(0.5f, carry.x, 0.5f * v.x);
        carry.y = fmaf(0.5f, carry.y, 0.5f * v.y);
        s[w * H2PW + c] = __floats2half2_rn(carry.x, carry.y);
    }
    __syncthreads();

    int we = w1 - 1 + LWARM; if (we > ROWLEN - 1) we = ROWLEN - 1;
    carry = __half22float2(s[we * H2PW + c]);
    for (int w = we - 1; w >= w1; --w) {
        const float2 v = __half22float2(s[w * H2PW + c]);
        carry.x = fmaf(0.5f, carry.x, 0.5f * v.x);
        carry.y = fmaf(0.5f, carry.y, 0.5f * v.y);
    }
    __syncthreads();

    #pragma unroll
    for (int w = w1 - 1; w >= w0; --w) {
        const float2 v = __half22float2(s[w * H2PW + c]);
        carry.x = fmaf(0.5f, carry.x, 0.5f * v.x);
        carry.y = fmaf(0.5f, carry.y, 0.5f * v.y);
        s[w * H2PW + c] = __floats2half2_rn(carry.x, carry.y);
    }
    __syncthreads();
}

__global__ void __launch_bounds__(THREADS, 3)
pass1_kernel(const float* __restrict__ x) {
    extern __shared__ __half2 s2[];
    uint4* s4 = reinterpret_cast<uint4*>(s2);

    const int    nh    = blockIdx.x;                // n*HH + h
    const int    n     = nh >> 9;
    const int    h     = nh & 511;
    const size_t xbase = (size_t)nh * (WW * CC);
    const size_t zbase = ((size_t)n * WW) * ZCOL + (size_t)h * CC;

    #pragma unroll
    for (int i = threadIdx.x; i < VECH; i += THREADS) {
        const int w = i >> 3;
        const int q = i & 7;
        const float4 a = *(const float4*)(x + xbase + (size_t)w * CC + q * 8);
        const float4 b = *(const float4*)(x + xbase + (size_t)w * CC + q * 8 + 4);
        __half2 hv[4];
        hv[0] = __floats2half2_rn(a.x, a.y);
        hv[1] = __floats2half2_rn(a.z, a.w);
        hv[2] = __floats2half2_rn(b.x, b.y);
        hv[3] = __floats2half2_rn(b.z, b.w);
        s4[w * 8 + q] = *(uint4*)hv;
    }
    __syncthreads();

    iir_scan_tile_h2(s2, threadIdx.x);

    #pragma unroll
    for (int i = threadIdx.x; i < VECH; i += THREADS) {
        const int w = i >> 3;
        const int q = i & 7;
        *(uint4*)(g_scratch + zbase + (size_t)w * ZCOL + q * 8) = s4[w * 8 + q];
    }
}

// ---- pass2: full-column tile; ONE barrier; backward scan fused with the
//      epilogue in 8-row batches (y_b stays in registers, never in smem) ----
__global__ void __launch_bounds__(THREADS, 3)
pass2_kernel(const float* __restrict__ alpha,
             float*       __restrict__ out) {
    extern __shared__ __half2 s2[];
    __shared__ __align__(16) float sm[CPB];

    const int    nw    = blockIdx.x;                // n*WW + w
    const int    n     = nw >> 9;
    const int    w     = nw & 511;
    const size_t zbase = ((size_t)n * WW + w) * ZCOL;
    const size_t obase = (size_t)n * (HH * WW * CC) + (size_t)w * CC;
    const __half* z0   = g_scratch + zbase;

    if (threadIdx.x < CPB)
        sm[threadIdx.x] = 1.0f / (1.0f + expf(-alpha[threadIdx.x]));

    const int c2    = threadIdx.x & 31;
    const int chunk = threadIdx.x >> 5;
    const int h0    = chunk * CLEN;
    const int h1    = h0 + CLEN;

    // ---- forward warm-up: gmem fp16 reads from the z blob ----
    int hs = h0 - LWARM; if (hs < 0) hs = 0;
    float2 carry = __half22float2(*(const __half2*)(z0 + (size_t)hs * CC + c2 * 2));
    for (int h = hs; h < h0; ++h) {
        const float2 v = __half22float2(*(const __half2*)(z0 + (size_t)h * CC + c2 * 2));
        carry.x = fmaf(0.5f, carry.x, 0.5f * v.x);
        carry.y = fmaf(0.5f, carry.y, 0.5f * v.y);
    }

    // ---- forward scan: gmem fp16 in, smem fp16 y_f out ----
    #pragma unroll 8
    for (int h = h0; h < h1; ++h) {
        const float2 v = __half22float2(*(const __half2*)(z0 + (size_t)h * CC + c2 * 2));
        carry.x = fmaf(0.5f, carry.x, 0.5f * v.x);
        carry.y = fmaf(0.5f, carry.y, 0.5f * v.y);
        s2[h * H2PW + c2] = __floats2half2_rn(carry.x, carry.y);
    }
    __syncthreads();   // the ONLY barrier: y_f finalized; smem read-only below

    // ---- backward warm-up (smem y_f; last chunk exact: carry = y_f[511]) ----
    int he = h1 - 1 + LWARM; if (he > ROWLEN - 1) he = ROWLEN - 1;
    float2 cb = __half22float2(s2[he * H2PW + c2]);
    for (int h = he - 1; h >= h1; --h) {
        const float2 v = __half22float2(s2[h * H2PW + c2]);
        cb.x = fmaf(0.5f, cb.x, 0.5f * v.x);
        cb.y = fmaf(0.5f, cb.y, 0.5f * v.y);
    }

    // Exact inverse of the W filter:
    //   w in [1,510]: x = 5 z[w] - 2 z[w-1] - 2 z[w+1]
    //   w = 0:        x = 2 z[0] - z[1]
    //   w = 511:      x = 3 z[511] - 2 z[510]
    float cm, c0, cp;
    const __half *zm, *zp;
    if (w == 0)        { cm = 0.f;  c0 = 2.f; cp = -1.f;
                         zm = z0;          zp = z0 + ZCOL; }
    else if (w == 511) { cm = -2.f; c0 = 3.f; cp = 0.f;
                         zm = z0 - ZCOL;   zp = z0; }
    else               { cm = -2.f; c0 = 5.f; cp = -2.f;
                         zm = z0 - ZCOL;   zp = z0 + ZCOL; }
    const float2 mv = *(const float2*)(&sm[c2 * 2]);

    // ---- backward scan + epilogue, fused in 8-row batches ----
    // Scan burst: pure smem reads + carry chain, y_b -> half2 regs
    // (same fp16 rounding point as R15's smem round-trip -> identical
    //  numerics). Epilogue burst: independent z loads + out stores,
    //  off the carry chain, full MLP.
    #pragma unroll
    for (int b = CLEN / BATCH - 1; b >= 0; --b) {
        const int hb = h0 + b * BATCH;
        __half2 yb[BATCH];
        #pragma unroll
        for (int j = BATCH - 1; j >= 0; --j) {
            const float2 v = __half22float2(s2[(hb + j) * H2PW + c2]);
            cb.x = fmaf(0.5f, cb.x, 0.5f * v.x);
            cb.y = fmaf(0.5f, cb.y, 0.5f * v.y);
            yb[j] = __floats2half2_rn(cb.x, cb.y);
        }
        #pragma unroll
        for (int j = 0; j < BATCH; ++j) {
            const int    h  = hb + j;
            const size_t zo = (size_t)h * CC + c2 * 2;
            const float2 v0 = __half22float2(*(const __half2*)(z0 + zo));
            const float2 vm = __half22float2(*(const __half2*)(zm + zo));
            const float2 vp = __half22float2(*(const __half2*)(zp + zo));
            const float2 yv = __half22float2(yb[j]);
            float2 o;
            const float xr = fmaf(c0, v0.x, fmaf(cm, vm.x, cp * vp.x));
            const float xi = fmaf(c0, v0.y, fmaf(cm, vm.y, cp * vp.y));
            o.x = fmaf(mv.x, yv.x - xr, xr);
            o.y = fmaf(mv.y, yv.y - xi, xi);
            *(float2*)(out + obase + (size_t)h * (WW * CC) + c2 * 2) = o;
        }
    }
}

extern "C" void kernel_launch(void* const* d_in, const int* in_sizes, int n_in,
                              void* d_out, int out_size) {
    const float* x     = (const float*)d_in[0];
    const float* alpha = (const float*)d_in[1];
    float*       out   = (float*)d_out;

    // >48KB dynamic smem opt-in (idempotent, capture-safe).
    cudaFuncSetAttribute(pass1_kernel,
                         cudaFuncAttributeMaxDynamicSharedMemorySize, SMEM_BYTES);
    cudaFuncSetAttribute(pass2_kernel,
                         cudaFuncAttributeMaxDynamicSharedMemorySize, SMEM_BYTES);

    pass1_kernel<<<NN * HH, THREADS, SMEM_BYTES>>>(x);
    pass2_kernel<<<NN * WW, THREADS, SMEM_BYTES>>>(alpha, out);
}